// round 7
// baseline (speedup 1.0000x reference)
#include <cuda_runtime.h>
#include <cstdint>

// CausalConv1d (R7): R6 + 2 batch rows per block to amortize the smem weight
// preamble (R6 spent ~1/3 of L1tex work reloading the 20KB weight tile per
// block). Same 1024-h tile serves rows b0 and b0+1; both rows' stream loads
// are front-batched (8x LDG.128/thread).
//
// out[b,h] = S0*w[h,0]+S1*w[h,1]+S2*w[h,2]+x*w[h,3]+bias[h]
// new_state[b,h,:] = {state[b,h,1], state[b,h,2], x[b,h]}

#define HIDDEN 4096
#define BATCH  4096
#define PAIRS  ((int64_t)BATCH * HIDDEN)
#define TPB    256
#define SEG    (TPB * 4)            // 1024 h per block
#define ROWS   2

__global__ void __launch_bounds__(TPB)
causal_conv1d_kernel(const float* __restrict__ x,
                     const float* __restrict__ state,
                     const float* __restrict__ weight,   // [HIDDEN,4] row-major
                     const float* __restrict__ bias,     // [HIDDEN]
                     float* __restrict__ out,            // [BATCH,HIDDEN]
                     float* __restrict__ new_state)      // [BATCH,HIDDEN,3]
{
    __shared__ float w_s[4][SEG];   // SoA: tap k, local h
    __shared__ float b_s[SEG];

    const int tid = threadIdx.x;
    const int seg = blockIdx.x & 3;                     // h segment [0,4)
    const int64_t b0 = (int64_t)(blockIdx.x >> 2) * ROWS;
    const int hb  = seg * SEG;                          // h base

    // ---- cooperative weight load + transpose (coalesced LDG, conflict-free STS) ----
    const float4* wslice = reinterpret_cast<const float4*>(weight + (int64_t)hb * 4);
    #pragma unroll
    for (int i = 0; i < 4; ++i) {
        int r = tid + i * TPB;                 // local h row [0,1024)
        float4 w = wslice[r];
        w_s[0][r] = w.x;
        w_s[1][r] = w.y;
        w_s[2][r] = w.z;
        w_s[3][r] = w.w;
    }
    reinterpret_cast<float4*>(b_s)[tid] =
        reinterpret_cast<const float4*>(bias + hb)[tid];
    __syncthreads();

    const int hl = tid * 4;                    // local h offset
    const float4 t0 = *reinterpret_cast<const float4*>(&w_s[0][hl]);
    const float4 t1 = *reinterpret_cast<const float4*>(&w_s[1][hl]);
    const float4 t2 = *reinterpret_cast<const float4*>(&w_s[2][hl]);
    const float4 t3 = *reinterpret_cast<const float4*>(&w_s[3][hl]);
    const float4 bv = *reinterpret_cast<const float4*>(&b_s[hl]);

    const int64_t pa = b0 * HIDDEN + hb + hl;          // row b0
    const int64_t pb = pa + HIDDEN;                    // row b0+1

    // ---- front-batched streaming loads: 8x LDG.128, fully coalesced ----
    const float4 xa  = *reinterpret_cast<const float4*>(x + pa);
    const float4 xb  = *reinterpret_cast<const float4*>(x + pb);
    const float4* spa = reinterpret_cast<const float4*>(state + pa * 3);
    const float4* spb = reinterpret_cast<const float4*>(state + pb * 3);
    const float4 a0 = spa[0], a1 = spa[1], a2 = spa[2];
    const float4 c0 = spb[0], c1 = spb[1], c2 = spb[2];

    // ---- compute row A ----
    float4 oa;
    oa.x = fmaf(a0.x, t0.x, fmaf(a0.y, t1.x, fmaf(a0.z, t2.x, fmaf(xa.x, t3.x, bv.x))));
    oa.y = fmaf(a0.w, t0.y, fmaf(a1.x, t1.y, fmaf(a1.y, t2.y, fmaf(xa.y, t3.y, bv.y))));
    oa.z = fmaf(a1.z, t0.z, fmaf(a1.w, t1.z, fmaf(a2.x, t2.z, fmaf(xa.z, t3.z, bv.z))));
    oa.w = fmaf(a2.y, t0.w, fmaf(a2.z, t1.w, fmaf(a2.w, t2.w, fmaf(xa.w, t3.w, bv.w))));

    // ---- compute row B ----
    float4 ob;
    ob.x = fmaf(c0.x, t0.x, fmaf(c0.y, t1.x, fmaf(c0.z, t2.x, fmaf(xb.x, t3.x, bv.x))));
    ob.y = fmaf(c0.w, t0.y, fmaf(c1.x, t1.y, fmaf(c1.y, t2.y, fmaf(xb.y, t3.y, bv.y))));
    ob.z = fmaf(c1.z, t0.z, fmaf(c1.w, t1.z, fmaf(c2.x, t2.z, fmaf(xb.z, t3.z, bv.z))));
    ob.w = fmaf(c2.y, t0.w, fmaf(c2.z, t1.w, fmaf(c2.w, t2.w, fmaf(xb.w, t3.w, bv.w))));

    // ---- new_state shuffles: flat = {S1,S2,X0, S4,S5,X1, S7,S8,X2, S10,S11,X3} ----
    const float4 na0 = make_float4(a0.y, a0.z, xa.x, a1.x);
    const float4 na1 = make_float4(a1.y, xa.y, a1.w, a2.x);
    const float4 na2 = make_float4(xa.z, a2.z, a2.w, xa.w);
    const float4 nb0 = make_float4(c0.y, c0.z, xb.x, c1.x);
    const float4 nb1 = make_float4(c1.y, xb.y, c1.w, c2.x);
    const float4 nb2 = make_float4(xb.z, c2.z, c2.w, xb.w);

    // ---- stores (8x STG.128, coalesced) ----
    *reinterpret_cast<float4*>(out + pa) = oa;
    *reinterpret_cast<float4*>(out + pb) = ob;
    float4* npa = reinterpret_cast<float4*>(new_state + pa * 3);
    npa[0] = na0;  npa[1] = na1;  npa[2] = na2;
    float4* npb = reinterpret_cast<float4*>(new_state + pb * 3);
    npb[0] = nb0;  npb[1] = nb1;  npb[2] = nb2;
}

extern "C" void kernel_launch(void* const* d_in, const int* in_sizes, int n_in,
                              void* d_out, int out_size)
{
    const float* x      = (const float*)d_in[0];
    const float* state  = (const float*)d_in[1];
    const float* weight = (const float*)d_in[2];
    const float* bias   = (const float*)d_in[3];

    float* out       = (float*)d_out;
    float* new_state = (float*)d_out + PAIRS;

    const int blocks = (int)(PAIRS / ((int64_t)SEG * ROWS));   // 8192
    causal_conv1d_kernel<<<blocks, TPB>>>(x, state, weight, bias, out, new_state);
}

// round 8
// speedup vs baseline: 1.0019x; 1.0019x over previous
#include <cuda_runtime.h>
#include <cstdint>

// CausalConv1d (R8): R6 (best: 81.6us, DRAM 77.8%) with evict-first (.cs)
// streaming stores. out/new_state (256MB) are write-once-never-read; default
// write-back policy makes them compete with the inbound read stream in L2.
// Evict-first lets LTS drain write bursts cleanly. Loads unchanged.
//
// out[b,h] = S0*w[h,0]+S1*w[h,1]+S2*w[h,2]+x*w[h,3]+bias[h]
// new_state[b,h,:] = {state[b,h,1], state[b,h,2], x[b,h]}

#define HIDDEN 4096
#define BATCH  4096
#define PAIRS  ((int64_t)BATCH * HIDDEN)
#define TPB    256
#define PAIRS_PER_BLOCK (TPB * 4)    // 1024 consecutive pairs, single row segment

__device__ __forceinline__ void stcs4(float* p, float4 v) {
    __stcs(reinterpret_cast<float4*>(p), v);
}

__global__ void __launch_bounds__(TPB)
causal_conv1d_kernel(const float* __restrict__ x,
                     const float* __restrict__ state,
                     const float* __restrict__ weight,   // [HIDDEN,4] row-major
                     const float* __restrict__ bias,     // [HIDDEN]
                     float* __restrict__ out,            // [BATCH,HIDDEN]
                     float* __restrict__ new_state)      // [BATCH,HIDDEN,3]
{
    __shared__ float w_s[4][PAIRS_PER_BLOCK];   // SoA: tap k, local h
    __shared__ float b_s[PAIRS_PER_BLOCK];

    const int tid = threadIdx.x;
    const int64_t blk_p0 = (int64_t)blockIdx.x * PAIRS_PER_BLOCK;
    const int hb = (int)(blk_p0 & (HIDDEN - 1));   // block's h base (1024-aligned)

    // ---- cooperative weight load + transpose (coalesced LDG, conflict-free STS) ----
    const float4* wslice = reinterpret_cast<const float4*>(weight + (int64_t)hb * 4);
    #pragma unroll
    for (int i = 0; i < 4; ++i) {
        int r = tid + i * TPB;                 // local h row [0,1024)
        float4 w = wslice[r];                  // lanes stride 16B -> coalesced
        w_s[0][r] = w.x;                       // lanes stride 4B -> conflict-free
        w_s[1][r] = w.y;
        w_s[2][r] = w.z;
        w_s[3][r] = w.w;
    }
    {
        const float4* bslice = reinterpret_cast<const float4*>(bias + hb);
        reinterpret_cast<float4*>(b_s)[tid] = bslice[tid];
    }
    __syncthreads();

    // ---- per-thread: 4 consecutive pairs ----
    const int64_t p0 = blk_p0 + (int64_t)tid * 4;
    const int hl = tid * 4;                    // local h offset

    const float4 t0 = *reinterpret_cast<const float4*>(&w_s[0][hl]);
    const float4 t1 = *reinterpret_cast<const float4*>(&w_s[1][hl]);
    const float4 t2 = *reinterpret_cast<const float4*>(&w_s[2][hl]);
    const float4 t3 = *reinterpret_cast<const float4*>(&w_s[3][hl]);
    const float4 bv = *reinterpret_cast<const float4*>(&b_s[hl]);

    // ---- streaming loads (4x LDG.128, fully coalesced) ----
    const float4 xv = *reinterpret_cast<const float4*>(x + p0);
    const float4* sp = reinterpret_cast<const float4*>(state + p0 * 3);
    const float4 s0 = sp[0];   // S0..S3
    const float4 s1 = sp[1];   // S4..S7
    const float4 s2 = sp[2];   // S8..S11

    // ---- compute: pair j taps = {S[3j],S[3j+1],S[3j+2],X[j]} ----
    float4 ov;
    ov.x = fmaf(s0.x, t0.x, fmaf(s0.y, t1.x, fmaf(s0.z, t2.x, fmaf(xv.x, t3.x, bv.x))));
    ov.y = fmaf(s0.w, t0.y, fmaf(s1.x, t1.y, fmaf(s1.y, t2.y, fmaf(xv.y, t3.y, bv.y))));
    ov.z = fmaf(s1.z, t0.z, fmaf(s1.w, t1.z, fmaf(s2.x, t2.z, fmaf(xv.z, t3.z, bv.z))));
    ov.w = fmaf(s2.y, t0.w, fmaf(s2.z, t1.w, fmaf(s2.w, t2.w, fmaf(xv.w, t3.w, bv.w))));

    // ---- new_state flat = {S1,S2,X0, S4,S5,X1, S7,S8,X2, S10,S11,X3} ----
    const float4 n0 = make_float4(s0.y, s0.z, xv.x, s1.x);
    const float4 n1 = make_float4(s1.y, xv.y, s1.w, s2.x);
    const float4 n2 = make_float4(xv.z, s2.z, s2.w, xv.w);

    // ---- evict-first streaming stores (4x STG.128.CS, coalesced) ----
    stcs4(out + p0, ov);
    float* nb = new_state + p0 * 3;
    stcs4(nb + 0, n0);
    stcs4(nb + 4, n1);
    stcs4(nb + 8, n2);
}

extern "C" void kernel_launch(void* const* d_in, const int* in_sizes, int n_in,
                              void* d_out, int out_size)
{
    const float* x      = (const float*)d_in[0];
    const float* state  = (const float*)d_in[1];
    const float* weight = (const float*)d_in[2];
    const float* bias   = (const float*)d_in[3];

    float* out       = (float*)d_out;
    float* new_state = (float*)d_out + PAIRS;

    const int blocks = (int)(PAIRS / PAIRS_PER_BLOCK);   // 16384
    causal_conv1d_kernel<<<blocks, TPB>>>(x, state, weight, bias, out, new_state);
}